// round 15
// baseline (speedup 1.0000x reference)
#include <cuda_runtime.h>
#include <cuda_bf16.h>
#include <float.h>

#define B_IMG 8
#define C_IN 64
#define H_IMG 288
#define W_IMG 512
#define NPIX (H_IMG * W_IMG)
#define NUM_FRAMES 9
#define K_ROIS 2
#define NCAND 16

// ---------------- scratch (device globals; no allocation allowed) ----------------
// NHWC bf16: element ((n*H + h)*W + w)*64 + c  (128 B per pixel)
__device__ __align__(16) __nv_bfloat16 g_xb[(size_t)B_IMG * H_IMG * W_IMG * 64];  // 151 MB
__device__ __align__(16) __nv_bfloat16 g_h1[(size_t)B_IMG * H_IMG * W_IMG * 64];  // 151 MB
__device__ __align__(16) __nv_bfloat16 g_w1b[64 * 584];   // pitched, smem-ready
__device__ __align__(16) __nv_bfloat16 g_w2b[32 * 584];
__device__ __align__(16) float g_heat[(size_t)B_IMG * NPIX];
__device__ int   g_cand[B_IMG * NCAND];
__device__ float g_rlogit[B_IMG * NCAND];

// ---------------- mma.sync bf16 m16n8k16, row.col, fp32 accum ----------------
__device__ __forceinline__ void mma16816(float* d,
    unsigned a0, unsigned a1, unsigned a2, unsigned a3, unsigned b0, unsigned b1) {
  asm volatile(
    "mma.sync.aligned.m16n8k16.row.col.f32.bf16.bf16.f32 "
    "{%0,%1,%2,%3}, {%4,%5,%6,%7}, {%8,%9}, {%0,%1,%2,%3};\n"
    : "+f"(d[0]), "+f"(d[1]), "+f"(d[2]), "+f"(d[3])
    : "r"(a0), "r"(a1), "r"(a2), "r"(a3), "r"(b0), "r"(b1));
}

__device__ __forceinline__ void ldsm_x4(unsigned& r0, unsigned& r1, unsigned& r2, unsigned& r3,
                                        unsigned addr) {
  asm volatile("ldmatrix.sync.aligned.m8n8.x4.shared.b16 {%0,%1,%2,%3}, [%4];\n"
    : "=r"(r0), "=r"(r1), "=r"(r2), "=r"(r3) : "r"(addr));
}

// smem: 4-row tiles => 6-row strips. xs [(r*66+col)][72ch] pitch 144B; ws [m][584] pitch 1168B
#define XS_BYTES (6 * 66 * 72 * 2)      // 57024
#define WSH_BYTES (32 * 584 * 2)        // 37376
#define SMEM_CONV (XS_BYTES + WSH_BYTES) // 94400 -> 2 blocks/SM

// refine smem layout (floats)
#define ROFF_WS1 0
#define ROFF_XP  (64 * 577)
#define ROFF_H1  (ROFF_XP + 64 * 28)
#define ROFF_PART (ROFF_H1 + 9 * 65)
#define ROFF_S2  (ROFF_PART + 32 * 9)
#define RSMEM_FLOATS (ROFF_S2 + 32)
#define RSMEM_BYTES (RSMEM_FLOATS * 4)   // ~158.5 KB

// ================= prep: fp32 NCHW -> bf16 NHWC (smem tile transpose) =================
__global__ __launch_bounds__(256) void prep_x_kernel(const float* __restrict__ x) {
  __shared__ __align__(16) __nv_bfloat16 s[64 * 72];
  const int n = blockIdx.z, h = blockIdx.y, wt = blockIdx.x * 64;
  const int tid = threadIdx.x;
  const int w = tid & 63, c0 = tid >> 6;
#pragma unroll
  for (int k = 0; k < 16; k++) {
    int c = c0 + k * 4;
    float v = x[(((size_t)(n * 64 + c) * H_IMG + h) * W_IMG) + wt + w];
    s[w * 72 + c] = __float2bfloat16(v);
  }
  __syncthreads();
  const size_t rowbase = ((size_t)(n * H_IMG + h) * W_IMG + wt) * 64;
#pragma unroll
  for (int i = tid; i < 512; i += 256) {
    int pix = i >> 3, seg = i & 7;
    *(uint4*)&g_xb[rowbase + (size_t)pix * 64 + seg * 8] =
        *(const uint4*)((const char*)s + pix * 144 + seg * 16);
  }
}

// weights into pitched layout: g_w*b[m*584 + tap*64 + c] = w[m,c,tap]; pads zeroed
__global__ __launch_bounds__(512) void prep_w_kernel(
    const float* __restrict__ w1, const float* __restrict__ w2) {
  const int stride = gridDim.x * blockDim.x;
  const int tid = blockIdx.x * blockDim.x + threadIdx.x;
  for (int i = tid; i < 64 * 584; i += stride) {
    int m = i / 584, j = i - m * 584;
    float v = 0.f;
    if (j < 576) { int tap = j >> 6, c = j & 63; v = w1[m * 576 + c * 9 + tap]; }
    g_w1b[i] = __float2bfloat16(v);
  }
  for (int i = tid; i < 32 * 584; i += stride) {
    int m = i / 584, j = i - m * 584;
    float v = 0.f;
    if (j < 576) { int tap = j >> 6, c = j & 63; v = w2[m * 576 + c * 9 + tap]; }
    g_w2b[i] = __float2bfloat16(v);
  }
}

// ================= conv1: 64->64 3x3 SAME + ReLU, NHWC bf16 out =================
// block: 4 rows x 64 px x 32 out-ch (z = n*2 + chhalf). 512 thr / 16 warps, 2 blocks/SM.
// warp: wn=wid&3 row; q=wid>>2: ph=q&1 (32-px half), ch16=q>>1 (16-ch half).
// A = pixels (2 m16 tiles), B = weights (one ldsm x4 -> two n8 tiles).
__global__ __launch_bounds__(512, 2) void conv1_kernel(const float* __restrict__ b1) {
  extern __shared__ char smem[];
  __nv_bfloat16* xs = (__nv_bfloat16*)smem;
  __nv_bfloat16* ws = (__nv_bfloat16*)(smem + XS_BYTES);
  const int tid = threadIdx.x;
  const int n  = blockIdx.z >> 1;
  const int chhalf = blockIdx.z & 1;
  const int h0 = blockIdx.y * 4;
  const int w0 = blockIdx.x * 64;

  {
    const uint4* src = (const uint4*)(g_w1b + chhalf * 32 * 584);
    uint4* dst = (uint4*)ws;
    for (int i = tid; i < WSH_BYTES / 16; i += 512) dst[i] = src[i];
  }
  // xs strip: 6 rows x 66 cols, 8x uint4 per pixel
  for (int i = tid; i < 3168; i += 512) {
    int pix = i >> 3, seg = i & 7;
    int r = pix / 66, col = pix - r * 66;
    int h = h0 - 1 + r, w = w0 - 1 + col;
    uint4 v = make_uint4(0u, 0u, 0u, 0u);
    if ((unsigned)h < (unsigned)H_IMG && (unsigned)w < (unsigned)W_IMG)
      v = *(const uint4*)&g_xb[((size_t)(n * H_IMG + h) * W_IMG + w) * 64 + seg * 8];
    *(uint4*)((char*)xs + pix * 144 + seg * 16) = v;
  }
  __syncthreads();

  const int lane = tid & 31, wid = tid >> 5;
  const int g = lane >> 2, tg = lane & 3;
  const int wn = wid & 3;
  const int q  = wid >> 2;
  const int ph = q & 1;
  const int ch16 = q >> 1;

  const unsigned ws_sh = (unsigned)__cvta_generic_to_shared(ws);
  const unsigned xs_sh = (unsigned)__cvta_generic_to_shared(xs);
  const unsigned aLaneX = (unsigned)(((lane >> 3) & 1) * 8 + (lane & 7)) * 144
                        + (unsigned)(lane >> 4) * 16;
  const unsigned wLaneB = (unsigned)((lane >> 4) * 8 + (lane & 7)) * 1168
                        + (unsigned)((lane >> 3) & 1) * 16;

  float acc[2][2][4];
#pragma unroll
  for (int a = 0; a < 2; a++)
#pragma unroll
    for (int p = 0; p < 2; p++)
#pragma unroll
      for (int r = 0; r < 4; r++) acc[a][p][r] = 0.f;

#pragma unroll 1
  for (int tap = 0; tap < 9; ++tap) {
    const int dy = tap / 3, dx = tap - dy * 3;
    const unsigned aTap = xs_sh + (unsigned)(((wn + dy) * 66) + dx + ph * 32) * 144 + aLaneX;
    const unsigned bTap = ws_sh + (unsigned)(ch16 * 16) * 1168 + (unsigned)tap * 128 + wLaneB;
#pragma unroll
    for (int cs = 0; cs < 4; ++cs) {
      unsigned b0, b1r, b2, b3;
      ldsm_x4(b0, b1r, b2, b3, bTap + cs * 32);   // 16 ch -> two n8 frags
#pragma unroll
      for (int np = 0; np < 2; ++np) {
        unsigned a0, a1, a2, a3;
        ldsm_x4(a0, a1, a2, a3, aTap + np * 2304 + cs * 32);  // 16 pixels
        mma16816(acc[np][0], a0, a1, a2, a3, b0, b1r);
        mma16816(acc[np][1], a0, a1, a2, a3, b2, b3);
      }
    }
  }

  // epilogue: pixel {ph*32+np*16+g, +8}, channel {chbase+nt*8+2tg, +1}
  const int h = h0 + wn;
  const size_t rowbase = ((size_t)(n * H_IMG + h) * W_IMG + w0) * 64;
  const int chbase = chhalf * 32 + ch16 * 16;
#pragma unroll
  for (int nt = 0; nt < 2; ++nt) {
    const int ch = chbase + nt * 8 + 2 * tg;
    const float bb0 = b1[ch], bb1 = b1[ch + 1];
#pragma unroll
    for (int np = 0; np < 2; ++np) {
      const int p0 = ph * 32 + np * 16 + g;
      float v0 = fmaxf(acc[np][nt][0] + bb0, 0.f);
      float v1 = fmaxf(acc[np][nt][1] + bb1, 0.f);
      float v2 = fmaxf(acc[np][nt][2] + bb0, 0.f);
      float v3 = fmaxf(acc[np][nt][3] + bb1, 0.f);
      *(__nv_bfloat162*)&g_h1[rowbase + (size_t)p0 * 64 + ch] = __floats2bfloat162_rn(v0, v1);
      *(__nv_bfloat162*)&g_h1[rowbase + (size_t)(p0 + 8) * 64 + ch] = __floats2bfloat162_rn(v2, v3);
    }
  }
}

// ===== conv2 (64->32 3x3 SAME + ReLU) fused with conv3 (1x1) -> fp32 logits =====
// block: 4 rows x 64 px x 32 ch. 512 thr / 16 warps, 2 blocks/SM.
// warp: wn=wid&3 row; pq=wid>>2 (16-px quarter). A = weights 32ch, B = pixels 16.
__global__ __launch_bounds__(512, 2) void conv2_kernel(
    const float* __restrict__ b2,
    const float* __restrict__ w3, const float* __restrict__ b3) {
  extern __shared__ char smem[];
  __nv_bfloat16* xs = (__nv_bfloat16*)smem;
  __nv_bfloat16* ws = (__nv_bfloat16*)(smem + XS_BYTES);
  const int tid = threadIdx.x;
  const int n  = blockIdx.z;
  const int h0 = blockIdx.y * 4;
  const int w0 = blockIdx.x * 64;

  {
    const uint4* src = (const uint4*)g_w2b;
    uint4* dst = (uint4*)ws;
    for (int i = tid; i < WSH_BYTES / 16; i += 512) dst[i] = src[i];
  }
  for (int i = tid; i < 3168; i += 512) {
    int pix = i >> 3, seg = i & 7;
    int r = pix / 66, col = pix - r * 66;
    int h = h0 - 1 + r, w = w0 - 1 + col;
    uint4 v = make_uint4(0u, 0u, 0u, 0u);
    if ((unsigned)h < (unsigned)H_IMG && (unsigned)w < (unsigned)W_IMG)
      v = *(const uint4*)&g_h1[((size_t)(n * H_IMG + h) * W_IMG + w) * 64 + seg * 8];
    *(uint4*)((char*)xs + pix * 144 + seg * 16) = v;
  }
  __syncthreads();

  const int lane = tid & 31, wid = tid >> 5;
  const int g = lane >> 2, tg = lane & 3;
  const int wn = wid & 3;
  const int pq = wid >> 2;   // 16-px quarter

  const unsigned ws_sh = (unsigned)__cvta_generic_to_shared(ws);
  const unsigned xs_sh = (unsigned)__cvta_generic_to_shared(xs);
  const unsigned aLane = (unsigned)(((lane >> 3) & 1) * 8 + (lane & 7)) * 1168
                       + (unsigned)(lane >> 4) * 16;
  const unsigned pixLane = (unsigned)((lane >> 4) * 8 + (lane & 7)) * 144
                         + (unsigned)((lane >> 3) & 1) * 16;

  float acc[2][2][4];
#pragma unroll
  for (int a = 0; a < 2; a++)
#pragma unroll
    for (int p = 0; p < 2; p++)
#pragma unroll
      for (int r = 0; r < 4; r++) acc[a][p][r] = 0.f;

#pragma unroll 1
  for (int tap = 0; tap < 9; ++tap) {
    const int dy = tap / 3, dx = tap - dy * 3;
    const unsigned bTap = xs_sh + (unsigned)(((wn + dy) * 66) + pq * 16 + dx) * 144 + pixLane;
    const unsigned aTap = ws_sh + aLane + (unsigned)tap * 128;
#pragma unroll
    for (int cs = 0; cs < 4; ++cs) {
      unsigned a0, a1, a2, a3, a4, a5, a6, a7;
      ldsm_x4(a0, a1, a2, a3, aTap + cs * 32);            // ch 0..15
      ldsm_x4(a4, a5, a6, a7, aTap + cs * 32 + 18688);    // ch 16..31
      unsigned b0, b1r, b2, b3;
      ldsm_x4(b0, b1r, b2, b3, bTap + cs * 32);           // 16 px
      mma16816(acc[0][0], a0, a1, a2, a3, b0, b1r);
      mma16816(acc[1][0], a4, a5, a6, a7, b0, b1r);
      mma16816(acc[0][1], a0, a1, a2, a3, b2, b3);
      mma16816(acc[1][1], a4, a5, a6, a7, b2, b3);
    }
  }

  const float w3v0 = w3[g],      w3v1 = w3[g + 8];
  const float w3v2 = w3[g + 16], w3v3 = w3[g + 24];
  const float b2v0 = b2[g],      b2v1 = b2[g + 8];
  const float b2v2 = b2[g + 16], b2v3 = b2[g + 24];
  const float b3v = b3[0];
  const int h = h0 + wn;
  float* heat = g_heat + (size_t)n * NPIX + (size_t)h * W_IMG + w0 + pq * 16;
#pragma unroll
  for (int nt = 0; nt < 2; ++nt) {
    float s0 = fmaxf(acc[0][nt][0] + b2v0, 0.f) * w3v0
             + fmaxf(acc[0][nt][2] + b2v1, 0.f) * w3v1
             + fmaxf(acc[1][nt][0] + b2v2, 0.f) * w3v2
             + fmaxf(acc[1][nt][2] + b2v3, 0.f) * w3v3;
    float s1 = fmaxf(acc[0][nt][1] + b2v0, 0.f) * w3v0
             + fmaxf(acc[0][nt][3] + b2v1, 0.f) * w3v1
             + fmaxf(acc[1][nt][1] + b2v2, 0.f) * w3v2
             + fmaxf(acc[1][nt][3] + b2v3, 0.f) * w3v3;
#pragma unroll
    for (int off = 4; off < 32; off <<= 1) {
      s0 += __shfl_xor_sync(0xffffffffu, s0, off);
      s1 += __shfl_xor_sync(0xffffffffu, s1, off);
    }
    if (g == 0) {
      heat[nt * 8 + 2 * tg]     = s0 + b3v;
      heat[nt * 8 + 2 * tg + 1] = s1 + b3v;
    }
  }
}

// ============== candidate top-16 per image (approx logits) ==============
__global__ __launch_bounds__(1024) void cand_kernel() {
  __shared__ float sv[2048];
  __shared__ int   si[2048];
  const int n = blockIdx.x;
  const int tid = threadIdx.x;
  const float* heat = g_heat + (size_t)n * NPIX;
  float v0 = -FLT_MAX, v1 = -FLT_MAX;
  int i0 = 0x7fffffff, i1 = 0x7fffffff;
  for (int i = tid; i < NPIX; i += 1024) {
    float v = heat[i];
    if (v > v0) { v1 = v0; i1 = i0; v0 = v; i0 = i; }
    else if (v > v1) { v1 = v; i1 = i; }
  }
  sv[tid * 2] = v0; si[tid * 2] = i0;
  sv[tid * 2 + 1] = v1; si[tid * 2 + 1] = i1;
  __syncthreads();
  if (tid == 0) {
    float bv[NCAND]; int bi[NCAND];
#pragma unroll
    for (int j = 0; j < NCAND; j++) { bv[j] = -FLT_MAX; bi[j] = 0x7fffffff; }
    for (int e = 0; e < 2048; e++) {
      float v = sv[e]; int id = si[e];
      if (v > bv[NCAND - 1] || (v == bv[NCAND - 1] && id < bi[NCAND - 1])) {
        int j = NCAND - 1;
        while (j > 0 && (v > bv[j - 1] || (v == bv[j - 1] && id < bi[j - 1]))) {
          bv[j] = bv[j - 1]; bi[j] = bi[j - 1]; j--;
        }
        bv[j] = v; bi[j] = id;
      }
    }
    for (int j = 0; j < NCAND; j++) g_cand[n * NCAND + j] = bi[j];
  }
}

// ============== exact fp32 refinement of candidate logits ==============
__global__ __launch_bounds__(288) void refine_kernel(
    const float* __restrict__ x,
    const float* __restrict__ w1, const float* __restrict__ b1,
    const float* __restrict__ w2, const float* __restrict__ b2,
    const float* __restrict__ w3, const float* __restrict__ b3) {
  extern __shared__ float rs[];
  float* ws1  = rs + ROFF_WS1;
  float* xp   = rs + ROFF_XP;
  float* h1p  = rs + ROFF_H1;
  float* part = rs + ROFF_PART;
  float* s2   = rs + ROFF_S2;
  const int cand = blockIdx.x;
  const int n = cand / NCAND;
  const int tid = threadIdx.x;
  const int pix = g_cand[cand];
  const int hc = pix / W_IMG, wc = pix % W_IMG;

  for (int i = tid; i < 64 * 576; i += 288) {
    int c = i / 576, j = i - c * 576;
    ws1[c * 577 + j] = w1[i];
  }
  for (int i = tid; i < 64 * 25; i += 288) {
    int c = i / 25, p = i - c * 25;
    int y = hc - 2 + p / 5, w = wc - 2 + p % 5;
    float v = 0.f;
    if ((unsigned)y < (unsigned)H_IMG && (unsigned)w < (unsigned)W_IMG)
      v = x[((size_t)(n * C_IN + c) * H_IMG + y) * W_IMG + w];
    xp[c * 28 + p] = v;
  }
  __syncthreads();

  for (int i = tid; i < 576; i += 288) {
    int pos = i >> 6, c = i & 63;
    int py = pos / 3, px = pos - py * 3;
    int yy = hc - 1 + py, xx = wc - 1 + px;
    float s = 0.f;
    if ((unsigned)yy < (unsigned)H_IMG && (unsigned)xx < (unsigned)W_IMG) {
      const float* wrow = ws1 + c * 577;
      for (int ic = 0; ic < 64; ic++) {
#pragma unroll
        for (int ty = 0; ty < 3; ty++)
#pragma unroll
          for (int tx = 0; tx < 3; tx++)
            s += xp[ic * 28 + (py + ty) * 5 + (px + tx)] * wrow[ic * 9 + ty * 3 + tx];
      }
      s = fmaxf(s + b1[c], 0.f);
    }
    h1p[pos * 65 + c] = s;
  }
  __syncthreads();

  {
    int ch = tid / 9, pos = tid - ch * 9;
    float s = 0.f;
    const float* wrow = w2 + (size_t)ch * 576;
    for (int ic = 0; ic < 64; ic++)
      s += h1p[pos * 65 + ic] * wrow[ic * 9 + pos];
    part[ch * 9 + pos] = s;
  }
  __syncthreads();
  if (tid < 32) {
    float s = 0.f;
#pragma unroll
    for (int p = 0; p < 9; p++) s += part[tid * 9 + p];
    s2[tid] = fmaxf(s + b2[tid], 0.f) * w3[tid];
  }
  __syncthreads();
  if (tid == 0) {
    float t = b3[0];
    for (int j = 0; j < 32; j++) t += s2[j];
    g_rlogit[cand] = t;
  }
}

// ============== final: top-2 per image from refined logits -> rois ==============
__global__ __launch_bounds__(96) void final_kernel(float* __restrict__ out) {
  __shared__ float hc_s[B_IMG * K_ROIS], wc_s[B_IMG * K_ROIS];
  const int tid = threadIdx.x;
  if (tid < B_IMG) {
    float v1 = -FLT_MAX, v2 = -FLT_MAX;
    int p1 = 0x7fffffff, p2 = 0x7fffffff;
    for (int j = 0; j < NCAND; j++) {
      float v = g_rlogit[tid * NCAND + j];
      int p = g_cand[tid * NCAND + j];
      if (v > v1 || (v == v1 && p < p1)) { v2 = v1; p2 = p1; v1 = v; p1 = p; }
      else if (v > v2 || (v == v2 && p < p2)) { v2 = v; p2 = p; }
    }
    hc_s[tid * 2]     = (float)(p1 / W_IMG);
    wc_s[tid * 2]     = (float)(p1 % W_IMG);
    hc_s[tid * 2 + 1] = (float)(p2 / W_IMG);
    wc_s[tid * 2 + 1] = (float)(p2 % W_IMG);
  }
  __syncthreads();
  for (int i = tid; i < NUM_FRAMES * B_IMG * K_ROIS * 4; i += 96) {
    int f = i / (B_IMG * K_ROIS * 4);
    int rem = i - f * (B_IMG * K_ROIS * 4);
    int j = rem >> 2, comp = rem & 3;
    float val;
    if (comp == 0)      val = (float)(j >> 1);
    else if (comp == 1) val = (float)f;
    else if (comp == 2) val = hc_s[j];
    else                val = wc_s[j];
    out[i] = val;
  }
}

// ---------------- launch ----------------
extern "C" void kernel_launch(void* const* d_in, const int* in_sizes, int n_in,
                              void* d_out, int out_size) {
  const float* x  = (const float*)d_in[0];
  const float* w1 = (const float*)d_in[1];
  const float* b1 = (const float*)d_in[2];
  const float* w2 = (const float*)d_in[3];
  const float* b2 = (const float*)d_in[4];
  const float* w3 = (const float*)d_in[5];
  const float* b3 = (const float*)d_in[6];
  float* out = (float*)d_out;

  cudaFuncSetAttribute(conv1_kernel, cudaFuncAttributeMaxDynamicSharedMemorySize, SMEM_CONV);
  cudaFuncSetAttribute(conv2_kernel, cudaFuncAttributeMaxDynamicSharedMemorySize, SMEM_CONV);
  cudaFuncSetAttribute(refine_kernel, cudaFuncAttributeMaxDynamicSharedMemorySize, RSMEM_BYTES);

  prep_x_kernel<<<dim3(8, 288, 8), 256>>>(x);
  prep_w_kernel<<<64, 512>>>(w1, w2);
  conv1_kernel<<<dim3(8, 72, 16), 512, SMEM_CONV>>>(b1);
  conv2_kernel<<<dim3(8, 72, 8), 512, SMEM_CONV>>>(b2, w3, b3);
  cand_kernel<<<8, 1024>>>();
  refine_kernel<<<B_IMG * NCAND, 288, RSMEM_BYTES>>>(x, w1, b1, w2, b2, w3, b3);
  final_kernel<<<1, 96>>>(out);
}